// round 4
// baseline (speedup 1.0000x reference)
#include <cuda_runtime.h>
#include <cuda_bf16.h>
#include <math.h>

#define DIMK   512
#define ALLNUM 8192
#define BATCH  2048
#define NCLS   1024
#define NPROX  8
#define TOPK   410
#define LAM    0.3f

// ---------------- scratch (device globals: no allocation allowed) ----------------
__device__ float g_centers[DIMK * ALLNUM];   // 16 MB  normalized proxies [DIM, ALLNUM]
__device__ float g_sim[BATCH * ALLNUM];      // 64 MB  input @ centers
__device__ float g_S[DIMK * NCLS];           //  2 MB  class-summed centers
__device__ float g_CL[ALLNUM * NCLS];        // 32 MB  centersT @ S
__device__ float g_invnorm[ALLNUM];
__device__ float g_rowloss[BATCH];
__device__ float g_regloss[ALLNUM];
__device__ int   g_tgt64;                    // 1 if target buffer is int64

// ---------------- target dtype detection (int64 vs int32) ----------------
__global__ void detect_kernel(const unsigned int* tw) {
    __shared__ unsigned int any;
    if (threadIdx.x == 0) any = 0u;
    __syncthreads();
    unsigned int local = 0u;
    // If int64: words[2i+1] are high halves of first 1024 targets -> all zero.
    // If int32: words[2i+1] are targets at odd indices -> essentially never all zero.
    for (int i = threadIdx.x; i < 1024; i += blockDim.x) local |= tw[2 * i + 1];
    atomicOr(&any, local);
    __syncthreads();
    if (threadIdx.x == 0) g_tgt64 = (any == 0u) ? 1 : 0;
}

// ---------------- column norms of Proxies [DIM, ALLNUM] ----------------
__global__ void colnorm_kernel(const float* __restrict__ P) {
    int j = blockIdx.x * blockDim.x + threadIdx.x;
    if (j >= ALLNUM) return;
    float acc = 0.0f;
#pragma unroll 8
    for (int d = 0; d < DIMK; d++) {
        float v = P[d * ALLNUM + j];
        acc += v * v;
    }
    float n = sqrtf(acc);
    g_invnorm[j] = 1.0f / fmaxf(n, 1e-12f);
}

// ---------------- centers = P * invnorm (column scale) ----------------
__global__ void centers_kernel(const float* __restrict__ P) {
    int idx = blockIdx.x * blockDim.x + threadIdx.x;    // over DIM*ALLNUM/4 float4s
    if (idx >= DIMK * ALLNUM / 4) return;
    int jq = idx % (ALLNUM / 4);
    const float4 pv = ((const float4*)P)[idx];
    const float4 iv = ((const float4*)g_invnorm)[jq];
    float4 r;
    r.x = pv.x * iv.x; r.y = pv.y * iv.y; r.z = pv.z * iv.z; r.w = pv.w * iv.w;
    ((float4*)g_centers)[idx] = r;
}

// ---------------- S[d,c] = sum over 8 proxies of class c ----------------
__global__ void classsum_kernel() {
    int idx = blockIdx.x * blockDim.x + threadIdx.x;    // over DIM*NCLS
    if (idx >= DIMK * NCLS) return;
    int d = idx / NCLS, c = idx % NCLS;
    const float4* p = (const float4*)(g_centers + d * ALLNUM + c * NPROX);
    float4 a = p[0], b = p[1];
    g_S[idx] = ((a.x + a.y) + (a.z + a.w)) + ((b.x + b.y) + (b.z + b.w));
}

// ---------------- classic SGEMM: C[M,N] = A[M,K] @ B[K,N] (all row-major) ----------------
__global__ void __launch_bounds__(256) sgemm_nn(const float* __restrict__ A,
                                                const float* __restrict__ Bm,
                                                float* __restrict__ Cm,
                                                int M, int N, int K) {
    const int BM = 128, BN = 128, BK = 8, TM = 8, TN = 8;
    __shared__ float As[BK][BM];
    __shared__ float Bs[BK][BN];
    const int tid = threadIdx.x;
    const int bx = blockIdx.x, by = blockIdx.y;
    const int tx = tid % (BN / TN);
    const int ty = tid / (BN / TN);
    float acc[TM][TN] = {};
    const float* Ab = A + (size_t)by * BM * K;
    const float* Bb = Bm + (size_t)bx * BN;
    const int a_row = tid / 2;
    const int a_col = (tid % 2) * 4;
    const int b_row = tid / 32;
    const int b_col = (tid % 32) * 4;
    for (int k0 = 0; k0 < K; k0 += BK) {
        float4 av = *(const float4*)(Ab + (size_t)a_row * K + k0 + a_col);
        As[a_col + 0][a_row] = av.x;
        As[a_col + 1][a_row] = av.y;
        As[a_col + 2][a_row] = av.z;
        As[a_col + 3][a_row] = av.w;
        float4 bv = *(const float4*)(Bb + (size_t)(k0 + b_row) * N + b_col);
        *(float4*)&Bs[b_row][b_col] = bv;
        __syncthreads();
#pragma unroll
        for (int k = 0; k < BK; k++) {
            float ra[TM], rb[TN];
#pragma unroll
            for (int i = 0; i < TM; i++) ra[i] = As[k][ty * TM + i];
#pragma unroll
            for (int j = 0; j < TN; j++) rb[j] = Bs[k][tx * TN + j];
#pragma unroll
            for (int i = 0; i < TM; i++)
#pragma unroll
                for (int j = 0; j < TN; j++) acc[i][j] += ra[i] * rb[j];
        }
        __syncthreads();
    }
    float* Cb = Cm + (size_t)(by * BM + ty * TM) * N + bx * BN + tx * TN;
#pragma unroll
    for (int i = 0; i < TM; i++)
#pragma unroll
        for (int j = 0; j < TN; j += 4)
            *(float4*)(Cb + (size_t)i * N + j) =
                make_float4(acc[i][j], acc[i][j + 1], acc[i][j + 2], acc[i][j + 3]);
}

// ---------------- SGEMM with A stored [K,M] row-major: C = A^T @ B ----------------
__global__ void __launch_bounds__(256) sgemm_tn(const float* __restrict__ A,
                                                const float* __restrict__ Bm,
                                                float* __restrict__ Cm,
                                                int M, int N, int K) {
    const int BM = 128, BN = 128, BK = 8, TM = 8, TN = 8;
    __shared__ float As[BK][BM];
    __shared__ float Bs[BK][BN];
    const int tid = threadIdx.x;
    const int bx = blockIdx.x, by = blockIdx.y;
    const int tx = tid % (BN / TN);
    const int ty = tid / (BN / TN);
    float acc[TM][TN] = {};
    const int a_row = tid / 32;          // k within tile
    const int a_col = (tid % 32) * 4;    // m within tile
    const int b_row = tid / 32;
    const int b_col = (tid % 32) * 4;
    for (int k0 = 0; k0 < K; k0 += BK) {
        float4 av = *(const float4*)(A + (size_t)(k0 + a_row) * M + by * BM + a_col);
        *(float4*)&As[a_row][a_col] = av;
        float4 bv = *(const float4*)(Bm + (size_t)(k0 + b_row) * N + bx * BN + b_col);
        *(float4*)&Bs[b_row][b_col] = bv;
        __syncthreads();
#pragma unroll
        for (int k = 0; k < BK; k++) {
            float ra[TM], rb[TN];
#pragma unroll
            for (int i = 0; i < TM; i++) ra[i] = As[k][ty * TM + i];
#pragma unroll
            for (int j = 0; j < TN; j++) rb[j] = Bs[k][tx * TN + j];
#pragma unroll
            for (int i = 0; i < TM; i++)
#pragma unroll
                for (int j = 0; j < TN; j++) acc[i][j] += ra[i] * rb[j];
        }
        __syncthreads();
    }
    float* Cb = Cm + (size_t)(by * BM + ty * TM) * N + bx * BN + tx * TN;
#pragma unroll
    for (int i = 0; i < TM; i++)
#pragma unroll
        for (int j = 0; j < TN; j += 4)
            *(float4*)(Cb + (size_t)i * N + j) =
                make_float4(acc[i][j], acc[i][j + 1], acc[i][j + 2], acc[i][j + 3]);
}

// ---------------- per-row: exact top-410 radix select + class-sum softmax CE ----------------
__device__ __forceinline__ unsigned int fkey(float v) {
    unsigned int b = __float_as_uint(v);
    return b ^ ((unsigned int)((int)b >> 31) | 0x80000000u);
}

__global__ void __launch_bounds__(256) topk_classify_kernel(const void* targ) {
    __shared__ float s_sim[ALLNUM];          // 32 KB
    __shared__ unsigned int s_hist[256];
    __shared__ float s_red[256];
    __shared__ float s_et;
    const int row = blockIdx.x;
    const int tid = threadIdx.x;

    int t;
    if (g_tgt64) t = (int)((const long long*)targ)[row];
    else         t = ((const int*)targ)[row];

    const float4* src = (const float4*)(g_sim + (size_t)row * ALLNUM);
    float4* dst = (float4*)s_sim;
    for (int i = tid; i < ALLNUM / 4; i += 256) dst[i] = src[i];
    __syncthreads();

    // 4-pass 8-bit radix select for the TOPK-th largest augmented key
    unsigned int prefix = 0u;
    int krem = TOPK;
    for (int shift = 24; shift >= 0; shift -= 8) {
        s_hist[tid] = 0u;
        __syncthreads();
        unsigned int mask_hi = (shift == 24) ? 0u : (0xFFFFFFFFu << (shift + 8));
        for (int j = tid; j < ALLNUM; j += 256) {
            float v = s_sim[j] + (((j >> 3) == t) ? 1000.0f : 0.0f);
            unsigned int key = fkey(v);
            if ((key & mask_hi) == prefix)
                atomicAdd(&s_hist[(key >> shift) & 0xFFu], 1u);
        }
        __syncthreads();
        // all threads redundantly scan (identical result, no broadcast needed)
        int cum = 0, chosen = 0;
        for (int b = 255; b >= 0; b--) {
            int h = (int)s_hist[b];
            if (cum + h >= krem) { chosen = b; break; }
            cum += h;
        }
        krem -= cum;
        prefix |= (unsigned int)chosen << shift;
        __syncthreads();   // protect hist before next pass's zeroing
    }
    const unsigned int T = prefix;

    // class sums over contiguous proxy groups (no atomics), masked softmax CE
    float esum = 0.0f;
    for (int c = tid; c < NCLS; c += 256) {
        float aug = (c == t) ? 1000.0f : 0.0f;
        float sum = 0.0f;
#pragma unroll
        for (int n = 0; n < NPROX; n++) {
            float v = s_sim[c * NPROX + n];
            if (fkey(v + aug) >= T) sum += v;
        }
        float e = (sum != 0.0f) ? expf(sum) : 0.0f;
        if (c == t) s_et = e;
        esum += e;
    }
    s_red[tid] = esum;
    __syncthreads();
    for (int s = 128; s > 0; s >>= 1) {
        if (tid < s) s_red[tid] += s_red[tid + s];
        __syncthreads();
    }
    if (tid == 0) {
        float p = s_et / (1e-8f + s_red[0]);
        g_rowloss[row] = -logf(p + 1e-20f);
    }
}

// ---------------- per-proxy regularizer: -log_softmax(CL[j,:])[j/8] ----------------
__global__ void __launch_bounds__(256) reg_kernel() {
    const int j = blockIdx.x;
    const int tid = threadIdx.x;
    const float* rowp = g_CL + (size_t)j * NCLS;
    __shared__ float s_red[256];

    float m = -INFINITY;
    for (int c = tid; c < NCLS; c += 256) m = fmaxf(m, rowp[c]);
    s_red[tid] = m;
    __syncthreads();
    for (int s = 128; s > 0; s >>= 1) {
        if (tid < s) s_red[tid] = fmaxf(s_red[tid], s_red[tid + s]);
        __syncthreads();
    }
    const float M = s_red[0];
    __syncthreads();

    float acc = 0.0f;
    for (int c = tid; c < NCLS; c += 256) acc += expf(rowp[c] - M);
    s_red[tid] = acc;
    __syncthreads();
    for (int s = 128; s > 0; s >>= 1) {
        if (tid < s) s_red[tid] += s_red[tid + s];
        __syncthreads();
    }
    if (tid == 0) {
        float lse = M + logf(s_red[0]);
        g_regloss[j] = lse - rowp[j >> 3];   // instance_label[j] = j/8
    }
}

// ---------------- final reduction ----------------
__global__ void __launch_bounds__(256) final_kernel(float* out, int out_size) {
    __shared__ float s1[256], s2[256];
    const int tid = threadIdx.x;
    float a = 0.0f, r = 0.0f;
    for (int i = tid; i < BATCH; i += 256)  a += g_rowloss[i];
    for (int i = tid; i < ALLNUM; i += 256) r += g_regloss[i];
    s1[tid] = a; s2[tid] = r;
    __syncthreads();
    for (int s = 128; s > 0; s >>= 1) {
        if (tid < s) { s1[tid] += s1[tid + s]; s2[tid] += s2[tid + s]; }
        __syncthreads();
    }
    if (tid == 0) {
        float lc  = s1[0] / (float)BATCH;
        float reg = s2[0] / (float)ALLNUM;
        out[0] = lc + LAM * reg;
        if (out_size > 1) out[1] = lc;
    }
}

// ---------------- launch ----------------
extern "C" void kernel_launch(void* const* d_in, const int* in_sizes, int n_in,
                              void* d_out, int out_size) {
    const float* input   = (const float*)d_in[0];      // [2048, 512]
    const void*  target  = d_in[1];                    // [2048] int32 or int64
    const float* proxies = (const float*)d_in[2];      // [512, 8192]
    // d_in[3] = instance_label, structurally j/8 (derived on device)
    float* out = (float*)d_out;

    float *centers, *sim, *S, *CL;
    cudaGetSymbolAddress((void**)&centers, g_centers);
    cudaGetSymbolAddress((void**)&sim,     g_sim);
    cudaGetSymbolAddress((void**)&S,       g_S);
    cudaGetSymbolAddress((void**)&CL,      g_CL);

    detect_kernel<<<1, 256>>>((const unsigned int*)target);
    colnorm_kernel<<<ALLNUM / 256, 256>>>(proxies);
    centers_kernel<<<(DIMK * ALLNUM / 4 + 255) / 256, 256>>>(proxies);
    classsum_kernel<<<(DIMK * NCLS + 255) / 256, 256>>>();

    // sim[2048,8192] = input[2048,512] @ centers[512,8192]
    {
        dim3 grid(ALLNUM / 128, BATCH / 128);
        sgemm_nn<<<grid, 256>>>(input, centers, sim, BATCH, ALLNUM, DIMK);
    }
    // CL[8192,1024] = centers^T[8192,512] @ S[512,1024]   (A stored [K,M])
    {
        dim3 grid(NCLS / 128, ALLNUM / 128);
        sgemm_tn<<<grid, 256>>>(centers, S, CL, ALLNUM, NCLS, DIMK);
    }

    topk_classify_kernel<<<BATCH, 256>>>(target);
    reg_kernel<<<ALLNUM, 256>>>();
    final_kernel<<<1, 256>>>(out, out_size);
}

// round 7
// speedup vs baseline: 2.0749x; 2.0749x over previous
#include <cuda_runtime.h>
#include <cuda_bf16.h>
#include <math.h>

#define DIMK   512
#define ALLNUM 8192
#define BATCH  2048
#define NCLS   1024
#define NPROX  8
#define TOPK   410
#define LAM    0.3f

// ---------------- scratch (device globals: no allocation allowed) ----------------
__device__ float g_centers[DIMK * ALLNUM];   // 16 MB  normalized proxies [DIM, ALLNUM]
__device__ float g_sim[BATCH * ALLNUM];      // 64 MB  input @ centers
__device__ float g_S[DIMK * NCLS];           //  2 MB  class-summed centers
__device__ float g_CL[ALLNUM * NCLS];        // 32 MB  centersT @ S
__device__ float g_invnorm[ALLNUM];
__device__ float g_rowloss[BATCH];
__device__ float g_regloss[ALLNUM];
__device__ int   g_tgt64;                    // 1 if target buffer is int64

// ---------------- target dtype detection (int64 vs int32) ----------------
__global__ void detect_kernel(const unsigned int* tw) {
    __shared__ unsigned int any;
    if (threadIdx.x == 0) any = 0u;
    __syncthreads();
    unsigned int local = 0u;
    for (int i = threadIdx.x; i < 1024; i += blockDim.x) local |= tw[2 * i + 1];
    atomicOr(&any, local);
    __syncthreads();
    if (threadIdx.x == 0) g_tgt64 = (any == 0u) ? 1 : 0;
}

// ---------------- column norms of Proxies [DIM, ALLNUM] ----------------
__global__ void colnorm_kernel(const float* __restrict__ P) {
    int j = blockIdx.x * blockDim.x + threadIdx.x;
    if (j >= ALLNUM) return;
    float acc = 0.0f;
#pragma unroll 8
    for (int d = 0; d < DIMK; d++) {
        float v = P[d * ALLNUM + j];
        acc += v * v;
    }
    float n = sqrtf(acc);
    g_invnorm[j] = 1.0f / fmaxf(n, 1e-12f);
}

// ---------------- centers = P * invnorm (column scale) ----------------
__global__ void centers_kernel(const float* __restrict__ P) {
    int idx = blockIdx.x * blockDim.x + threadIdx.x;
    if (idx >= DIMK * ALLNUM / 4) return;
    int jq = idx % (ALLNUM / 4);
    const float4 pv = ((const float4*)P)[idx];
    const float4 iv = ((const float4*)g_invnorm)[jq];
    float4 r;
    r.x = pv.x * iv.x; r.y = pv.y * iv.y; r.z = pv.z * iv.z; r.w = pv.w * iv.w;
    ((float4*)g_centers)[idx] = r;
}

// ---------------- S[d,c] = sum over 8 proxies of class c ----------------
__global__ void classsum_kernel() {
    int idx = blockIdx.x * blockDim.x + threadIdx.x;
    if (idx >= DIMK * NCLS) return;
    int d = idx / NCLS, c = idx % NCLS;
    const float4* p = (const float4*)(g_centers + d * ALLNUM + c * NPROX);
    float4 a = p[0], b = p[1];
    g_S[idx] = ((a.x + a.y) + (a.z + a.w)) + ((b.x + b.y) + (b.z + b.w));
}

// ---------------- tf32 helpers ----------------
__device__ __forceinline__ float tf32r(float x) {
    unsigned int y;
    asm("cvt.rna.tf32.f32 %0, %1;" : "=r"(y) : "f"(x));
    return __uint_as_float(y);
}

__device__ __forceinline__ void mma8(float* c, const unsigned* a, const unsigned* b) {
    asm volatile(
        "mma.sync.aligned.m16n8k8.row.col.f32.tf32.tf32.f32 "
        "{%0,%1,%2,%3}, {%4,%5,%6,%7}, {%8,%9}, {%0,%1,%2,%3};"
        : "+f"(c[0]), "+f"(c[1]), "+f"(c[2]), "+f"(c[3])
        : "r"(a[0]), "r"(a[1]), "r"(a[2]), "r"(a[3]), "r"(b[0]), "r"(b[1]));
}

// ---------------- tensor-core tf32 GEMM: C[M,N] = A @ B ----------------
// TRANSA=0: A stored [M,K] row-major (K contiguous)
// TRANSA=1: A stored [K,M] row-major (M contiguous), compute A^T @ B
// B stored [K,N] row-major. BM=BN=128, BK=32. 256 threads = 8 warps,
// warp tile 32(M) x 64(N) = 2 x 8 m16n8k8 tiles.
template <int TRANSA>
__global__ void __launch_bounds__(256, 2) mma_gemm_tf32(const float* __restrict__ A,
                                                        const float* __restrict__ B,
                                                        float* __restrict__ C,
                                                        int M, int N, int K) {
    const int SA = 132, SB = 132;
    __shared__ float As[32 * SA];
    __shared__ float Bs[32 * SB];
    const int tid = threadIdx.x;
    const int lane = tid & 31;
    const int wid = tid >> 5;
    const int gid = lane >> 2;     // 0..7
    const int tig = lane & 3;      // 0..3
    const int wm = (wid & 3) * 32; // warp M offset within tile
    const int wn = (wid >> 2) * 64;// warp N offset within tile
    const int m0 = blockIdx.y * 128;
    const int n0 = blockIdx.x * 128;

    float acc[2][8][4] = {};

    for (int k0 = 0; k0 < K; k0 += 32) {
        if (TRANSA == 0) {
            // A[M,K]: load float4 along K, transpose into As[k][m]
#pragma unroll
            for (int i = 0; i < 4; i++) {
                int q = tid + i * 256;
                int m = q >> 3, kq = q & 7;
                float4 v = *(const float4*)(A + (size_t)(m0 + m) * K + k0 + kq * 4);
                As[(kq * 4 + 0) * SA + m] = tf32r(v.x);
                As[(kq * 4 + 1) * SA + m] = tf32r(v.y);
                As[(kq * 4 + 2) * SA + m] = tf32r(v.z);
                As[(kq * 4 + 3) * SA + m] = tf32r(v.w);
            }
        } else {
            // A[K,M]: direct float4 into As[k][m]
#pragma unroll
            for (int i = 0; i < 4; i++) {
                int q = tid + i * 256;
                int k = q >> 5, mq = q & 31;
                float4 v = *(const float4*)(A + (size_t)(k0 + k) * M + m0 + mq * 4);
                v.x = tf32r(v.x); v.y = tf32r(v.y); v.z = tf32r(v.z); v.w = tf32r(v.w);
                *(float4*)&As[k * SA + mq * 4] = v;
            }
        }
#pragma unroll
        for (int i = 0; i < 4; i++) {
            int q = tid + i * 256;
            int k = q >> 5, nq = q & 31;
            float4 v = *(const float4*)(B + (size_t)(k0 + k) * N + n0 + nq * 4);
            v.x = tf32r(v.x); v.y = tf32r(v.y); v.z = tf32r(v.z); v.w = tf32r(v.w);
            *(float4*)&Bs[k * SB + nq * 4] = v;
        }
        __syncthreads();

#pragma unroll
        for (int ks = 0; ks < 4; ks++) {
            const int kk = ks * 8;
            unsigned a[2][4], b[8][2];
#pragma unroll
            for (int mt = 0; mt < 2; mt++) {
                int r = wm + mt * 16 + gid;
                a[mt][0] = __float_as_uint(As[(kk + tig) * SA + r]);
                a[mt][1] = __float_as_uint(As[(kk + tig) * SA + r + 8]);
                a[mt][2] = __float_as_uint(As[(kk + tig + 4) * SA + r]);
                a[mt][3] = __float_as_uint(As[(kk + tig + 4) * SA + r + 8]);
            }
#pragma unroll
            for (int nt = 0; nt < 8; nt++) {
                int cc = wn + nt * 8 + gid;
                b[nt][0] = __float_as_uint(Bs[(kk + tig) * SB + cc]);
                b[nt][1] = __float_as_uint(Bs[(kk + tig + 4) * SB + cc]);
            }
#pragma unroll
            for (int mt = 0; mt < 2; mt++)
#pragma unroll
                for (int nt = 0; nt < 8; nt++)
                    mma8(acc[mt][nt], a[mt], b[nt]);
        }
        __syncthreads();
    }

#pragma unroll
    for (int mt = 0; mt < 2; mt++) {
        int r = m0 + wm + mt * 16 + gid;
#pragma unroll
        for (int nt = 0; nt < 8; nt++) {
            int cpos = n0 + wn + nt * 8 + 2 * tig;
            *(float2*)(C + (size_t)r * N + cpos) =
                make_float2(acc[mt][nt][0], acc[mt][nt][1]);
            *(float2*)(C + (size_t)(r + 8) * N + cpos) =
                make_float2(acc[mt][nt][2], acc[mt][nt][3]);
        }
    }
}

// ---------------- per-row: exact top-410 radix select + class-sum softmax CE ----------------
__device__ __forceinline__ unsigned int fkey(float v) {
    unsigned int b = __float_as_uint(v);
    return b ^ ((unsigned int)((int)b >> 31) | 0x80000000u);
}

__global__ void __launch_bounds__(256) topk_classify_kernel(const void* targ) {
    __shared__ float s_sim[ALLNUM];          // 32 KB
    __shared__ unsigned int s_hist[256];
    __shared__ float s_red[256];
    __shared__ float s_et;
    const int row = blockIdx.x;
    const int tid = threadIdx.x;

    int t;
    if (g_tgt64) t = (int)((const long long*)targ)[row];
    else         t = ((const int*)targ)[row];

    const float4* src = (const float4*)(g_sim + (size_t)row * ALLNUM);
    float4* dst = (float4*)s_sim;
    for (int i = tid; i < ALLNUM / 4; i += 256) dst[i] = src[i];
    __syncthreads();

    unsigned int prefix = 0u;
    int krem = TOPK;
    for (int shift = 24; shift >= 0; shift -= 8) {
        s_hist[tid] = 0u;
        __syncthreads();
        unsigned int mask_hi = (shift == 24) ? 0u : (0xFFFFFFFFu << (shift + 8));
        for (int j = tid; j < ALLNUM; j += 256) {
            float v = s_sim[j] + (((j >> 3) == t) ? 1000.0f : 0.0f);
            unsigned int key = fkey(v);
            if ((key & mask_hi) == prefix)
                atomicAdd(&s_hist[(key >> shift) & 0xFFu], 1u);
        }
        __syncthreads();
        int cum = 0, chosen = 0;
        for (int b = 255; b >= 0; b--) {
            int h = (int)s_hist[b];
            if (cum + h >= krem) { chosen = b; break; }
            cum += h;
        }
        krem -= cum;
        prefix |= (unsigned int)chosen << shift;
        __syncthreads();
    }
    const unsigned int T = prefix;

    float esum = 0.0f;
    for (int c = tid; c < NCLS; c += 256) {
        float aug = (c == t) ? 1000.0f : 0.0f;
        float sum = 0.0f;
#pragma unroll
        for (int n = 0; n < NPROX; n++) {
            float v = s_sim[c * NPROX + n];
            if (fkey(v + aug) >= T) sum += v;
        }
        float e = (sum != 0.0f) ? expf(sum) : 0.0f;
        if (c == t) s_et = e;
        esum += e;
    }
    s_red[tid] = esum;
    __syncthreads();
    for (int s = 128; s > 0; s >>= 1) {
        if (tid < s) s_red[tid] += s_red[tid + s];
        __syncthreads();
    }
    if (tid == 0) {
        float p = s_et / (1e-8f + s_red[0]);
        g_rowloss[row] = -logf(p + 1e-20f);
    }
}

// ---------------- per-proxy regularizer: -log_softmax(CL[j,:])[j/8] ----------------
__global__ void __launch_bounds__(256) reg_kernel() {
    const int j = blockIdx.x;
    const int tid = threadIdx.x;
    const float* rowp = g_CL + (size_t)j * NCLS;
    __shared__ float s_red[256];

    float m = -INFINITY;
    for (int c = tid; c < NCLS; c += 256) m = fmaxf(m, rowp[c]);
    s_red[tid] = m;
    __syncthreads();
    for (int s = 128; s > 0; s >>= 1) {
        if (tid < s) s_red[tid] = fmaxf(s_red[tid], s_red[tid + s]);
        __syncthreads();
    }
    const float M = s_red[0];
    __syncthreads();

    float acc = 0.0f;
    for (int c = tid; c < NCLS; c += 256) acc += expf(rowp[c] - M);
    s_red[tid] = acc;
    __syncthreads();
    for (int s = 128; s > 0; s >>= 1) {
        if (tid < s) s_red[tid] += s_red[tid + s];
        __syncthreads();
    }
    if (tid == 0) {
        float lse = M + logf(s_red[0]);
        g_regloss[j] = lse - rowp[j >> 3];
    }
}

// ---------------- final reduction ----------------
__global__ void __launch_bounds__(256) final_kernel(float* out, int out_size) {
    __shared__ float s1[256], s2[256];
    const int tid = threadIdx.x;
    float a = 0.0f, r = 0.0f;
    for (int i = tid; i < BATCH; i += 256)  a += g_rowloss[i];
    for (int i = tid; i < ALLNUM; i += 256) r += g_regloss[i];
    s1[tid] = a; s2[tid] = r;
    __syncthreads();
    for (int s = 128; s > 0; s >>= 1) {
        if (tid < s) { s1[tid] += s1[tid + s]; s2[tid] += s2[tid + s]; }
        __syncthreads();
    }
    if (tid == 0) {
        float lc  = s1[0] / (float)BATCH;
        float reg = s2[0] / (float)ALLNUM;
        out[0] = lc + LAM * reg;
        if (out_size > 1) out[1] = lc;
    }
}

// ---------------- launch ----------------
extern "C" void kernel_launch(void* const* d_in, const int* in_sizes, int n_in,
                              void* d_out, int out_size) {
    const float* input   = (const float*)d_in[0];      // [2048, 512]
    const void*  target  = d_in[1];                    // [2048] int32 or int64
    const float* proxies = (const float*)d_in[2];      // [512, 8192]
    float* out = (float*)d_out;

    float *centers, *sim, *S, *CL;
    cudaGetSymbolAddress((void**)&centers, g_centers);
    cudaGetSymbolAddress((void**)&sim,     g_sim);
    cudaGetSymbolAddress((void**)&S,       g_S);
    cudaGetSymbolAddress((void**)&CL,      g_CL);

    detect_kernel<<<1, 256>>>((const unsigned int*)target);
    colnorm_kernel<<<ALLNUM / 256, 256>>>(proxies);
    centers_kernel<<<(DIMK * ALLNUM / 4 + 255) / 256, 256>>>(proxies);
    classsum_kernel<<<(DIMK * NCLS + 255) / 256, 256>>>();

    // sim[2048,8192] = input[2048,512] @ centers[512,8192]  (tensor cores, tf32)
    {
        dim3 grid(ALLNUM / 128, BATCH / 128);
        mma_gemm_tf32<0><<<grid, 256>>>(input, centers, sim, BATCH, ALLNUM, DIMK);
    }
    // CL[8192,1024] = centers^T @ S[512,1024]  (A stored [K,M]; tensor cores, tf32)
    {
        dim3 grid(NCLS / 128, ALLNUM / 128);
        mma_gemm_tf32<1><<<grid, 256>>>(centers, S, CL, ALLNUM, NCLS, DIMK);
    }

    topk_classify_kernel<<<BATCH, 256>>>(target);
    reg_kernel<<<ALLNUM, 256>>>();
    final_kernel<<<1, 256>>>(out, out_size);
}

// round 8
// speedup vs baseline: 2.7613x; 1.3308x over previous
#include <cuda_runtime.h>
#include <cuda_bf16.h>
#include <math.h>

#define DIMK   512
#define ALLNUM 8192
#define BATCH  2048
#define NCLS   1024
#define NPROX  8
#define TOPK   410
#define LAM    0.3f

// ---------------- scratch (device globals: no allocation allowed) ----------------
__device__ float g_centers[DIMK * ALLNUM];   // 16 MB
__device__ float g_sim[BATCH * ALLNUM];      // 64 MB
__device__ float g_S[DIMK * NCLS];           //  2 MB
__device__ float g_CL[ALLNUM * NCLS];        // 32 MB
__device__ float g_sumsq[ALLNUM];
__device__ float g_rowloss[BATCH];
__device__ float g_regloss[ALLNUM];
__device__ int   g_tgt64;

// ---------------- target dtype detection (int64 vs int32) ----------------
__global__ void detect_kernel(const unsigned int* tw) {
    __shared__ unsigned int any;
    if (threadIdx.x == 0) any = 0u;
    __syncthreads();
    unsigned int local = 0u;
    for (int i = threadIdx.x; i < 1024; i += blockDim.x) local |= tw[2 * i + 1];
    atomicOr(&any, local);
    __syncthreads();
    if (threadIdx.x == 0) g_tgt64 = (any == 0u) ? 1 : 0;
}

// ---------------- partial column sum-of-squares (full-chip parallel) ----------------
__global__ void __launch_bounds__(256) sumsq_kernel(const float* __restrict__ P) {
    int j = blockIdx.x * 256 + threadIdx.x;
    int d0 = blockIdx.y * 64;
    float acc = 0.0f;
#pragma unroll 8
    for (int d = 0; d < 64; d++) {
        float v = P[(size_t)(d0 + d) * ALLNUM + j];
        acc += v * v;
    }
    atomicAdd(&g_sumsq[j], acc);
}

// ---------------- centers = P / max(||col||, 1e-12) ----------------
__global__ void __launch_bounds__(256) centers_kernel(const float* __restrict__ P) {
    int idx = blockIdx.x * 256 + threadIdx.x;          // over DIM*ALLNUM/4
    int jq = idx % (ALLNUM / 4);
    const float4 pv = ((const float4*)P)[idx];
    const float4 s = ((const float4*)g_sumsq)[jq];
    float4 r;
    r.x = pv.x / fmaxf(sqrtf(s.x), 1e-12f);
    r.y = pv.y / fmaxf(sqrtf(s.y), 1e-12f);
    r.z = pv.z / fmaxf(sqrtf(s.z), 1e-12f);
    r.w = pv.w / fmaxf(sqrtf(s.w), 1e-12f);
    ((float4*)g_centers)[idx] = r;
}

// ---------------- S[d,c] = sum over 8 proxies of class c ----------------
__global__ void classsum_kernel() {
    int idx = blockIdx.x * blockDim.x + threadIdx.x;
    if (idx >= DIMK * NCLS) return;
    int d = idx / NCLS, c = idx % NCLS;
    const float4* p = (const float4*)(g_centers + d * ALLNUM + c * NPROX);
    float4 a = p[0], b = p[1];
    g_S[idx] = ((a.x + a.y) + (a.z + a.w)) + ((b.x + b.y) + (b.z + b.w));
}

// ---------------- tf32 MMA (raw f32 operands: HW truncates to tf32) ----------------
__device__ __forceinline__ void mma8(float* c, const unsigned* a, const unsigned* b) {
    asm volatile(
        "mma.sync.aligned.m16n8k8.row.col.f32.tf32.tf32.f32 "
        "{%0,%1,%2,%3}, {%4,%5,%6,%7}, {%8,%9}, {%0,%1,%2,%3};"
        : "+f"(c[0]), "+f"(c[1]), "+f"(c[2]), "+f"(c[3])
        : "r"(a[0]), "r"(a[1]), "r"(a[2]), "r"(a[3]), "r"(b[0]), "r"(b[1]));
}

#define CPA16(dst, src) \
    asm volatile("cp.async.cg.shared.global [%0], [%1], 16;" ::"r"(dst), "l"(src))

// ---------------- pipelined tf32 GEMM body ----------------
// TRANSA=0: A [M,K] row-major. As staged [m][k] stride 36.
// TRANSA=1: A [K,M] row-major (compute A^T@B). As staged [k][m] stride 132.
// B [K,N] row-major, Bs staged [k][n] stride 132. BM=BN=128, BK=32.
// 256 threads, warp tile 32x64, 2-stage cp.async double buffer.
template <int TRANSA>
__device__ __forceinline__ void gemm_path(const float* __restrict__ A,
                                          const float* __restrict__ B,
                                          float* __restrict__ C,
                                          int M, int N, int K,
                                          int bx, int by, float* sm) {
    const int tid = threadIdx.x;
    const int lane = tid & 31, wid = tid >> 5;
    const int gid = lane >> 2, tig = lane & 3;
    const int wm = (wid & 3) * 32, wn = (wid >> 2) * 64;
    const int m0 = by * 128, n0 = bx * 128;
    const int ASZ = TRANSA ? 32 * 132 : 128 * 36;
    const int STG = ASZ + 32 * 132;

    float acc[2][8][4] = {};
    unsigned sbase = (unsigned)__cvta_generic_to_shared(sm);

    auto issue = [&](int st, int k0) {
        unsigned as = sbase + (unsigned)(st * STG) * 4u;
        unsigned bs = as + (unsigned)ASZ * 4u;
        if (TRANSA == 0) {
#pragma unroll
            for (int i = 0; i < 4; i++) {
                int q = tid + i * 256;
                int m = q >> 3, kc = q & 7;
                CPA16(as + (unsigned)(m * 36 + kc * 4) * 4u,
                      A + (size_t)(m0 + m) * K + k0 + kc * 4);
            }
        } else {
#pragma unroll
            for (int i = 0; i < 4; i++) {
                int q = tid + i * 256;
                int k = q >> 5, mc = q & 31;
                CPA16(as + (unsigned)(k * 132 + mc * 4) * 4u,
                      A + (size_t)(k0 + k) * M + m0 + mc * 4);
            }
        }
#pragma unroll
        for (int i = 0; i < 4; i++) {
            int q = tid + i * 256;
            int k = q >> 5, nc = q & 31;
            CPA16(bs + (unsigned)(k * 132 + nc * 4) * 4u,
                  B + (size_t)(k0 + k) * N + n0 + nc * 4);
        }
    };

    issue(0, 0);
    asm volatile("cp.async.commit_group;");

    const int NIT = K / 32;
    for (int it = 0; it < NIT; it++) {
        if (it + 1 < NIT) issue((it + 1) & 1, (it + 1) * 32);
        asm volatile("cp.async.commit_group;");
        asm volatile("cp.async.wait_group 1;");
        __syncthreads();

        float* As = sm + (it & 1) * STG;
        float* Bs = As + ASZ;
#pragma unroll
        for (int ks = 0; ks < 4; ks++) {
            const int kk = ks * 8;
            unsigned a[2][4], b[8][2];
#pragma unroll
            for (int mt = 0; mt < 2; mt++) {
                int r = wm + mt * 16 + gid;
                if (TRANSA == 0) {
                    a[mt][0] = __float_as_uint(As[r * 36 + kk + tig]);
                    a[mt][1] = __float_as_uint(As[(r + 8) * 36 + kk + tig]);
                    a[mt][2] = __float_as_uint(As[r * 36 + kk + tig + 4]);
                    a[mt][3] = __float_as_uint(As[(r + 8) * 36 + kk + tig + 4]);
                } else {
                    a[mt][0] = __float_as_uint(As[(kk + tig) * 132 + r]);
                    a[mt][1] = __float_as_uint(As[(kk + tig) * 132 + r + 8]);
                    a[mt][2] = __float_as_uint(As[(kk + tig + 4) * 132 + r]);
                    a[mt][3] = __float_as_uint(As[(kk + tig + 4) * 132 + r + 8]);
                }
            }
#pragma unroll
            for (int nt = 0; nt < 8; nt++) {
                int cc = wn + nt * 8 + gid;
                b[nt][0] = __float_as_uint(Bs[(kk + tig) * 132 + cc]);
                b[nt][1] = __float_as_uint(Bs[(kk + tig + 4) * 132 + cc]);
            }
#pragma unroll
            for (int mt = 0; mt < 2; mt++)
#pragma unroll
                for (int nt = 0; nt < 8; nt++)
                    mma8(acc[mt][nt], a[mt], b[nt]);
        }
        __syncthreads();
    }

#pragma unroll
    for (int mt = 0; mt < 2; mt++) {
        int r = m0 + wm + mt * 16 + gid;
#pragma unroll
        for (int nt = 0; nt < 8; nt++) {
            int cpos = n0 + wn + nt * 8 + 2 * tig;
            *(float2*)(C + (size_t)r * N + cpos) =
                make_float2(acc[mt][nt][0], acc[mt][nt][1]);
            *(float2*)(C + (size_t)(r + 8) * N + cpos) =
                make_float2(acc[mt][nt][2], acc[mt][nt][3]);
        }
    }
}

#define SIM_BLOCKS ((BATCH / 128) * (ALLNUM / 128))   // 1024
#define CL_BLOCKS  ((ALLNUM / 128) * (NCLS / 128))    // 512
#define GEMM_SMEM  ((128 * 36 + 32 * 132) * 2 * 4)    // 70656 bytes (max of 2 paths)

__global__ void __launch_bounds__(256) gemm_fused(const float* __restrict__ input) {
    extern __shared__ float sm[];
    int b = blockIdx.x;
    if (b < SIM_BLOCKS) {
        gemm_path<0>(input, g_centers, g_sim, BATCH, ALLNUM, DIMK,
                     b % (ALLNUM / 128), b / (ALLNUM / 128), sm);
    } else {
        b -= SIM_BLOCKS;
        gemm_path<1>(g_centers, g_S, g_CL, ALLNUM, NCLS, DIMK,
                     b % (NCLS / 128), b / (NCLS / 128), sm);
    }
}

// ---------------- per-row: exact top-410 radix select + class-sum softmax CE ----------------
__device__ __forceinline__ unsigned int fkey(float v) {
    unsigned int b = __float_as_uint(v);
    return b ^ ((unsigned int)((int)b >> 31) | 0x80000000u);
}

__global__ void __launch_bounds__(256) topk_classify_kernel(const void* targ) {
    __shared__ float s_sim[ALLNUM];          // 32 KB
    __shared__ unsigned int s_hist[256];
    __shared__ float s_red[256];
    __shared__ float s_et;
    const int row = blockIdx.x;
    const int tid = threadIdx.x;

    int t;
    if (g_tgt64) t = (int)((const long long*)targ)[row];
    else         t = ((const int*)targ)[row];

    const float4* src = (const float4*)(g_sim + (size_t)row * ALLNUM);
    float4* dst = (float4*)s_sim;
    for (int i = tid; i < ALLNUM / 4; i += 256) dst[i] = src[i];
    __syncthreads();

    unsigned int prefix = 0u;
    int krem = TOPK;
    for (int shift = 24; shift >= 0; shift -= 8) {
        s_hist[tid] = 0u;
        __syncthreads();
        unsigned int mask_hi = (shift == 24) ? 0u : (0xFFFFFFFFu << (shift + 8));
        for (int j = tid; j < ALLNUM; j += 256) {
            float v = s_sim[j] + (((j >> 3) == t) ? 1000.0f : 0.0f);
            unsigned int key = fkey(v);
            if ((key & mask_hi) == prefix)
                atomicAdd(&s_hist[(key >> shift) & 0xFFu], 1u);
        }
        __syncthreads();
        int cum = 0, chosen = 0;
        for (int b = 255; b >= 0; b--) {
            int h = (int)s_hist[b];
            if (cum + h >= krem) { chosen = b; break; }
            cum += h;
        }
        krem -= cum;
        prefix |= (unsigned int)chosen << shift;
        __syncthreads();
    }
    const unsigned int T = prefix;

    float esum = 0.0f;
    for (int c = tid; c < NCLS; c += 256) {
        float aug = (c == t) ? 1000.0f : 0.0f;
        float sum = 0.0f;
#pragma unroll
        for (int n = 0; n < NPROX; n++) {
            float v = s_sim[c * NPROX + n];
            if (fkey(v + aug) >= T) sum += v;
        }
        float e = (sum != 0.0f) ? expf(sum) : 0.0f;
        if (c == t) s_et = e;
        esum += e;
    }
    s_red[tid] = esum;
    __syncthreads();
    for (int s = 128; s > 0; s >>= 1) {
        if (tid < s) s_red[tid] += s_red[tid + s];
        __syncthreads();
    }
    if (tid == 0) {
        float p = s_et / (1e-8f + s_red[0]);
        g_rowloss[row] = -logf(p + 1e-20f);
    }
}

// ---------------- per-proxy regularizer: -log_softmax(CL[j,:])[j/8] ----------------
// |CL[j,c]| = |<unit_j, sum of 8 unit vecs>| <= 8, so a fixed shift of 8 is
// overflow-safe: lse = 8 + log(sum exp(x-8)). One float4 per thread (1024 cols).
__global__ void __launch_bounds__(256) reg_kernel() {
    const int j = blockIdx.x;
    const int tid = threadIdx.x;
    const float* rowp = g_CL + (size_t)j * NCLS;
    __shared__ float s_red[8];

    float4 v = ((const float4*)rowp)[tid];
    float acc = expf(v.x - 8.0f) + expf(v.y - 8.0f) +
                expf(v.z - 8.0f) + expf(v.w - 8.0f);
#pragma unroll
    for (int o = 16; o > 0; o >>= 1) acc += __shfl_xor_sync(0xFFFFFFFFu, acc, o);
    if ((tid & 31) == 0) s_red[tid >> 5] = acc;
    __syncthreads();
    if (tid == 0) {
        float s = 0.0f;
#pragma unroll
        for (int w = 0; w < 8; w++) s += s_red[w];
        g_regloss[j] = 8.0f + logf(s) - rowp[j >> 3];
    }
}

// ---------------- final reduction ----------------
__global__ void __launch_bounds__(256) final_kernel(float* out, int out_size) {
    __shared__ float s1[256], s2[256];
    const int tid = threadIdx.x;
    float a = 0.0f, r = 0.0f;
    for (int i = tid; i < BATCH; i += 256)  a += g_rowloss[i];
    for (int i = tid; i < ALLNUM; i += 256) r += g_regloss[i];
    s1[tid] = a; s2[tid] = r;
    __syncthreads();
    for (int s = 128; s > 0; s >>= 1) {
        if (tid < s) { s1[tid] += s1[tid + s]; s2[tid] += s2[tid + s]; }
        __syncthreads();
    }
    if (tid == 0) {
        float lc  = s1[0] / (float)BATCH;
        float reg = s2[0] / (float)ALLNUM;
        out[0] = lc + LAM * reg;
        if (out_size > 1) out[1] = lc;
    }
}

// ---------------- launch ----------------
extern "C" void kernel_launch(void* const* d_in, const int* in_sizes, int n_in,
                              void* d_out, int out_size) {
    const float* input   = (const float*)d_in[0];      // [2048, 512]
    const void*  target  = d_in[1];                    // [2048] int32 or int64
    const float* proxies = (const float*)d_in[2];      // [512, 8192]
    float* out = (float*)d_out;

    float* sumsq;
    cudaGetSymbolAddress((void**)&sumsq, g_sumsq);

    cudaFuncSetAttribute(gemm_fused,
                         cudaFuncAttributeMaxDynamicSharedMemorySize, GEMM_SMEM);

    detect_kernel<<<1, 256>>>((const unsigned int*)target);
    cudaMemsetAsync(sumsq, 0, ALLNUM * sizeof(float));
    {
        dim3 grid(ALLNUM / 256, DIMK / 64);            // 32 x 8 = 256 blocks
        sumsq_kernel<<<grid, 256>>>(proxies);
    }
    centers_kernel<<<DIMK * ALLNUM / 4 / 256, 256>>>(proxies);
    classsum_kernel<<<(DIMK * NCLS + 255) / 256, 256>>>();

    gemm_fused<<<SIM_BLOCKS + CL_BLOCKS, 256, GEMM_SMEM>>>(input);

    topk_classify_kernel<<<BATCH, 256>>>(target);
    reg_kernel<<<ALLNUM, 256>>>();
    final_kernel<<<1, 256>>>(out, out_size);
}

// round 15
// speedup vs baseline: 3.8230x; 1.3845x over previous
#include <cuda_runtime.h>
#include <cuda_bf16.h>
#include <math.h>

#define DIMK   512
#define ALLNUM 8192
#define BATCH  2048
#define NCLS   1024
#define NPROX  8
#define TOPK   410
#define LAM    0.3f

// ---------------- scratch (device globals: no allocation allowed) ----------------
__device__ __nv_bfloat16 g_inp_bf[BATCH * DIMK];    //  2 MB  input, bf16
__device__ __nv_bfloat16 g_centT[ALLNUM * DIMK];    //  8 MB  normalized centers^T [8192,512]
__device__ __nv_bfloat16 g_St[NCLS * DIMK];         //  1 MB  class-summed centers^T [1024,512]
__device__ float g_sim[BATCH * ALLNUM];             // 64 MB
__device__ float g_CL[ALLNUM * NCLS];               // 32 MB
__device__ float g_sumsq[ALLNUM];
__device__ float g_rowloss[BATCH];
__device__ float g_regloss[ALLNUM];
__device__ int   g_tgt64;

// ---------------- target dtype detection (int64 vs int32) ----------------
__global__ void detect_kernel(const unsigned int* tw) {
    __shared__ unsigned int any;
    if (threadIdx.x == 0) any = 0u;
    __syncthreads();
    unsigned int local = 0u;
    for (int i = threadIdx.x; i < 1024; i += blockDim.x) local |= tw[2 * i + 1];
    atomicOr(&any, local);
    __syncthreads();
    if (threadIdx.x == 0) g_tgt64 = (any == 0u) ? 1 : 0;
}

// ---------------- partial column sum-of-squares ----------------
__global__ void __launch_bounds__(256) sumsq_kernel(const float* __restrict__ P) {
    int j = blockIdx.x * 256 + threadIdx.x;
    int d0 = blockIdx.y * 64;
    float acc = 0.0f;
#pragma unroll 8
    for (int d = 0; d < 64; d++) {
        float v = P[(size_t)(d0 + d) * ALLNUM + j];
        acc += v * v;
    }
    atomicAdd(&g_sumsq[j], acc);
}

// ---------------- input -> bf16 ----------------
__global__ void __launch_bounds__(256) inpcvt_kernel(const float* __restrict__ X) {
    int idx = blockIdx.x * 256 + threadIdx.x;   // over BATCH*DIMK/4
    float4 v = ((const float4*)X)[idx];
    __nv_bfloat162* o = (__nv_bfloat162*)g_inp_bf;
    o[idx * 2 + 0] = __floats2bfloat162_rn(v.x, v.y);
    o[idx * 2 + 1] = __floats2bfloat162_rn(v.z, v.w);
}

// ---------------- centT[j][d] = bf16(P[d][j] / max(||col j||,1e-12)) ----------------
__global__ void __launch_bounds__(256) transpose_kernel(const float* __restrict__ P) {
    __shared__ float tile[32][33];
    int j0 = blockIdx.x * 32, d0 = blockIdx.y * 32;
    int tx = threadIdx.x & 31, ty = threadIdx.x >> 5;   // 32 x 8
#pragma unroll
    for (int ry = 0; ry < 4; ry++) {
        int r = ty + ry * 8;                            // d within tile
        float inv = 1.0f / fmaxf(sqrtf(g_sumsq[j0 + tx]), 1e-12f);
        tile[r][tx] = P[(size_t)(d0 + r) * ALLNUM + j0 + tx] * inv;
    }
    __syncthreads();
#pragma unroll
    for (int ry = 0; ry < 4; ry++) {
        int r = ty + ry * 8;                            // j within tile
        g_centT[(size_t)(j0 + r) * DIMK + d0 + tx] = __float2bfloat16(tile[tx][r]);
    }
}

// ---------------- St[c][d] = bf16( sum_{n<8} centT[8c+n][d] ) ----------------
__global__ void __launch_bounds__(256) classsum_kernel() {
    int idx = blockIdx.x * 256 + threadIdx.x;           // over NCLS * DIMK/2
    int c = idx >> 8, d2 = idx & 255;
    const __nv_bfloat162* src = (const __nv_bfloat162*)g_centT;
    float sx = 0.0f, sy = 0.0f;
#pragma unroll
    for (int n = 0; n < NPROX; n++) {
        float2 v = __bfloat1622float2(src[(size_t)(c * NPROX + n) * (DIMK / 2) + d2]);
        sx += v.x; sy += v.y;
    }
    ((__nv_bfloat162*)g_St)[idx] = __floats2bfloat162_rn(sx, sy);
}

// ---------------- bf16 legacy MMA ----------------
__device__ __forceinline__ void mma16(float* c, const unsigned* a, const unsigned* b) {
    asm volatile(
        "mma.sync.aligned.m16n8k16.row.col.f32.bf16.bf16.f32 "
        "{%0,%1,%2,%3}, {%4,%5,%6,%7}, {%8,%9}, {%0,%1,%2,%3};"
        : "+f"(c[0]), "+f"(c[1]), "+f"(c[2]), "+f"(c[3])
        : "r"(a[0]), "r"(a[1]), "r"(a[2]), "r"(a[3]), "r"(b[0]), "r"(b[1]));
}
#define CPA16(dst, src) \
    asm volatile("cp.async.cg.shared.global [%0], [%1], 16;" ::"r"(dst), "l"(src))

#define SIM_BLOCKS ((BATCH / 128) * (ALLNUM / 128))   // 1024
#define CL_BLOCKS  ((ALLNUM / 128) * (NCLS / 128))    // 512
// per-stage tile: 128 rows x 72 bf16 (64 data + 8 pad) = 18432 B
#define TROWB  144
#define TILE_B (128 * TROWB)
#define STG_B  (2 * TILE_B)
#define GEMM_SMEM (2 * STG_B)                         // 73728 B

// ---------------- fused bf16 GEMM: C = A @ B^T ----------------
// A [M,512] bf16 row-major, B [N,512] bf16 row-major, C f32 [M,N].
// BM=BN=128, BK=64. 256 threads = 8 warps, warp tile 32x64
// (2 m-tiles x 8 n-tiles of m16n8k16). 2-stage cp.async double buffer.
__global__ void __launch_bounds__(256) gemm_fused() {
    extern __shared__ char dyn[];
    const int tid = threadIdx.x;
    const int lane = tid & 31, wid = tid >> 5;
    const int gid = lane >> 2, tig = lane & 3;
    const int wm = (wid & 3) * 32, wn = (wid >> 2) * 64;

    int b = blockIdx.x;
    const __nv_bfloat16 *A, *B;
    float* C;
    int m0, n0, ldc;
    if (b < SIM_BLOCKS) {
        A = g_inp_bf; B = g_centT; C = g_sim; ldc = ALLNUM;
        m0 = (b / (ALLNUM / 128)) * 128;
        n0 = (b % (ALLNUM / 128)) * 128;
    } else {
        b -= SIM_BLOCKS;
        A = g_centT; B = g_St; C = g_CL; ldc = NCLS;
        m0 = (b / (NCLS / 128)) * 128;
        n0 = (b % (NCLS / 128)) * 128;
    }

    unsigned sbase = (unsigned)__cvta_generic_to_shared(dyn);

    float acc[2][8][4] = {};

    // stage loader: per stage, A tile then B tile; 128B of data per row,
    // 8 x 16B cp.async per row, 1024 per tile, 4 per thread per tile.
    auto issue = [&](int st, int k0) {
        unsigned abase = sbase + (unsigned)st * STG_B;
        unsigned bbase = abase + TILE_B;
#pragma unroll
        for (int i = 0; i < 4; i++) {
            int q = tid + i * 256;
            int row = q >> 3, u = q & 7;
            CPA16(abase + (unsigned)(row * TROWB + u * 16),
                  A + (size_t)(m0 + row) * DIMK + k0 + u * 8);
        }
#pragma unroll
        for (int i = 0; i < 4; i++) {
            int q = tid + i * 256;
            int row = q >> 3, u = q & 7;
            CPA16(bbase + (unsigned)(row * TROWB + u * 16),
                  B + (size_t)(n0 + row) * DIMK + k0 + u * 8);
        }
    };

    issue(0, 0);
    asm volatile("cp.async.commit_group;");

    const int NIT = DIMK / 64;                          // 8
    for (int it = 0; it < NIT; it++) {
        if (it + 1 < NIT) issue((it + 1) & 1, (it + 1) * 64);
        asm volatile("cp.async.commit_group;");
        asm volatile("cp.async.wait_group 1;");
        __syncthreads();

        const unsigned* As = (const unsigned*)(dyn + (it & 1) * STG_B);
        const unsigned* Bs = As + TILE_B / 4;
        const int RW = TROWB / 4;                       // 36 words per row
#pragma unroll
        for (int ks = 0; ks < 4; ks++) {
            const int kw = ks * 8;                      // word offset of k-step
            unsigned a[2][4], bb[8][2];
#pragma unroll
            for (int mt = 0; mt < 2; mt++) {
                int r = wm + mt * 16 + gid;
                a[mt][0] = As[r * RW + kw + tig];
                a[mt][1] = As[(r + 8) * RW + kw + tig];
                a[mt][2] = As[r * RW + kw + 4 + tig];
                a[mt][3] = As[(r + 8) * RW + kw + 4 + tig];
            }
#pragma unroll
            for (int nt = 0; nt < 8; nt++) {
                int cc = wn + nt * 8 + gid;
                bb[nt][0] = Bs[cc * RW + kw + tig];
                bb[nt][1] = Bs[cc * RW + kw + 4 + tig];
            }
#pragma unroll
            for (int mt = 0; mt < 2; mt++)
#pragma unroll
                for (int nt = 0; nt < 8; nt++)
                    mma16(acc[mt][nt], a[mt], bb[nt]);
        }
        __syncthreads();
    }

#pragma unroll
    for (int mt = 0; mt < 2; mt++) {
        int r = m0 + wm + mt * 16 + gid;
#pragma unroll
        for (int nt = 0; nt < 8; nt++) {
            int cpos = n0 + wn + nt * 8 + 2 * tig;
            *(float2*)(C + (size_t)r * ldc + cpos) =
                make_float2(acc[mt][nt][0], acc[mt][nt][1]);
            *(float2*)(C + (size_t)(r + 8) * ldc + cpos) =
                make_float2(acc[mt][nt][2], acc[mt][nt][3]);
        }
    }
}

// ---------------- per-row: exact top-410 radix select + class-sum softmax CE ----------------
__device__ __forceinline__ unsigned int fkey(float v) {
    unsigned int b = __float_as_uint(v);
    return b ^ ((unsigned int)((int)b >> 31) | 0x80000000u);
}

__global__ void __launch_bounds__(256) topk_classify_kernel(const void* targ) {
    __shared__ float s_sim[ALLNUM];
    __shared__ unsigned int s_hist[256];
    __shared__ float s_red[256];
    __shared__ float s_et;
    const int row = blockIdx.x;
    const int tid = threadIdx.x;

    int t;
    if (g_tgt64) t = (int)((const long long*)targ)[row];
    else         t = ((const int*)targ)[row];

    const float4* src = (const float4*)(g_sim + (size_t)row * ALLNUM);
    float4* dst = (float4*)s_sim;
    for (int i = tid; i < ALLNUM / 4; i += 256) dst[i] = src[i];
    __syncthreads();

    unsigned int prefix = 0u;
    int krem = TOPK;
    for (int shift = 24; shift >= 0; shift -= 8) {
        s_hist[tid] = 0u;
        __syncthreads();
        unsigned int mask_hi = (shift == 24) ? 0u : (0xFFFFFFFFu << (shift + 8));
        for (int j = tid; j < ALLNUM; j += 256) {
            float v = s_sim[j] + (((j >> 3) == t) ? 1000.0f : 0.0f);
            unsigned int key = fkey(v);
            if ((key & mask_hi) == prefix)
                atomicAdd(&s_hist[(key >> shift) & 0xFFu], 1u);
        }
        __syncthreads();
        int cum = 0, chosen = 0;
        for (int b = 255; b >= 0; b--) {
            int h = (int)s_hist[b];
            if (cum + h >= krem) { chosen = b; break; }
            cum += h;
        }
        krem -= cum;
        prefix |= (unsigned int)chosen << shift;
        __syncthreads();
    }
    const unsigned int T = prefix;

    float esum = 0.0f;
    for (int c = tid; c < NCLS; c += 256) {
        float aug = (c == t) ? 1000.0f : 0.0f;
        float sum = 0.0f;
#pragma unroll
        for (int n = 0; n < NPROX; n++) {
            float v = s_sim[c * NPROX + n];
            if (fkey(v + aug) >= T) sum += v;
        }
        float e = (sum != 0.0f) ? expf(sum) : 0.0f;
        if (c == t) s_et = e;
        esum += e;
    }
    s_red[tid] = esum;
    __syncthreads();
    for (int s = 128; s > 0; s >>= 1) {
        if (tid < s) s_red[tid] += s_red[tid + s];
        __syncthreads();
    }
    if (tid == 0) {
        float p = s_et / (1e-8f + s_red[0]);
        g_rowloss[row] = -logf(p + 1e-20f);
    }
}

// ---------------- per-proxy regularizer ----------------
// |CL[j,c]| <= ~8 analytically, fixed shift of 8 is overflow-safe.
__global__ void __launch_bounds__(256) reg_kernel() {
    const int j = blockIdx.x;
    const int tid = threadIdx.x;
    const float* rowp = g_CL + (size_t)j * NCLS;
    __shared__ float s_red[8];

    float4 v = ((const float4*)rowp)[tid];
    float acc = expf(v.x - 8.0f) + expf(v.y - 8.0f) +
                expf(v.z - 8.0f) + expf(v.w - 8.0f);
#pragma unroll
    for (int o = 16; o > 0; o >>= 1) acc += __shfl_xor_sync(0xFFFFFFFFu, acc, o);
    if ((tid & 31) == 0) s_red[tid >> 5] = acc;
    __syncthreads();
    if (tid == 0) {
        float s = 0.0f;
#pragma unroll
        for (int w = 0; w < 8; w++) s += s_red[w];
        g_regloss[j] = 8.0f + logf(s) - rowp[j >> 3];
    }
}

// ---------------- final reduction ----------------
__global__ void __launch_bounds__(256) final_kernel(float* out, int out_size) {
    __shared__ float s1[256], s2[256];
    const int tid = threadIdx.x;
    float a = 0.0f, r = 0.0f;
    for (int i = tid; i < BATCH; i += 256)  a += g_rowloss[i];
    for (int i = tid; i < ALLNUM; i += 256) r += g_regloss[i];
    s1[tid] = a; s2[tid] = r;
    __syncthreads();
    for (int s = 128; s > 0; s >>= 1) {
        if (tid < s) { s1[tid] += s1[tid + s]; s2[tid] += s2[tid + s]; }
        __syncthreads();
    }
    if (tid == 0) {
        float lc  = s1[0] / (float)BATCH;
        float reg = s2[0] / (float)ALLNUM;
        out[0] = lc + LAM * reg;
        if (out_size > 1) out[1] = lc;
    }
}

// ---------------- launch ----------------
extern "C" void kernel_launch(void* const* d_in, const int* in_sizes, int n_in,
                              void* d_out, int out_size) {
    const float* input   = (const float*)d_in[0];      // [2048, 512]
    const void*  target  = d_in[1];                    // [2048] int32 or int64
    const float* proxies = (const float*)d_in[2];      // [512, 8192]
    float* out = (float*)d_out;

    float* sumsq;
    cudaGetSymbolAddress((void**)&sumsq, g_sumsq);

    cudaFuncSetAttribute(gemm_fused,
                         cudaFuncAttributeMaxDynamicSharedMemorySize, GEMM_SMEM);

    detect_kernel<<<1, 256>>>((const unsigned int*)target);
    cudaMemsetAsync(sumsq, 0, ALLNUM * sizeof(float));
    {
        dim3 grid(ALLNUM / 256, DIMK / 64);
        sumsq_kernel<<<grid, 256>>>(proxies);
    }
    inpcvt_kernel<<<BATCH * DIMK / 4 / 256, 256>>>(input);
    {
        dim3 grid(ALLNUM / 32, DIMK / 32);
        transpose_kernel<<<grid, 256>>>(proxies);
    }
    classsum_kernel<<<NCLS * (DIMK / 2) / 256, 256>>>();

    gemm_fused<<<SIM_BLOCKS + CL_BLOCKS, 256, GEMM_SMEM>>>();

    topk_classify_kernel<<<BATCH, 256>>>(target);
    reg_kernel<<<ALLNUM, 256>>>();
    final_kernel<<<1, 256>>>(out, out_size);
}

// round 16
// speedup vs baseline: 4.3014x; 1.1251x over previous
#include <cuda_runtime.h>
#include <cuda_bf16.h>
#include <math.h>

#define DIMK   512
#define ALLNUM 8192
#define BATCH  2048
#define NCLS   1024
#define NPROX  8
#define TOPK   410
#define LAM    0.3f

// ---------------- scratch (device globals: no allocation allowed) ----------------
__device__ __nv_bfloat16 g_inp_bf[BATCH * DIMK];    //  2 MB  input, bf16
__device__ __nv_bfloat16 g_centT[ALLNUM * DIMK];    //  8 MB  normalized centers^T [8192,512]
__device__ __nv_bfloat16 g_St[NCLS * DIMK];         //  1 MB  class-summed centers^T [1024,512]
__device__ float g_sim[BATCH * ALLNUM];             // 64 MB
__device__ float g_sumsq[ALLNUM];
__device__ float g_rowloss[BATCH];
__device__ float g_regpart[ALLNUM];                 // per-proxy sum of exp(CL-8)
__device__ float g_diag[ALLNUM];                    // CL[j, j>>3]
__device__ int   g_tgt64;

// ---------------- target dtype detection (int64 vs int32) ----------------
__global__ void detect_kernel(const unsigned int* tw) {
    __shared__ unsigned int any;
    if (threadIdx.x == 0) any = 0u;
    __syncthreads();
    unsigned int local = 0u;
    for (int i = threadIdx.x; i < 1024; i += blockDim.x) local |= tw[2 * i + 1];
    atomicOr(&any, local);
    __syncthreads();
    if (threadIdx.x == 0) g_tgt64 = (any == 0u) ? 1 : 0;
}

// ---------------- partial column sum-of-squares ----------------
__global__ void __launch_bounds__(256) sumsq_kernel(const float* __restrict__ P) {
    int j = blockIdx.x * 256 + threadIdx.x;
    int d0 = blockIdx.y * 64;
    float acc = 0.0f;
#pragma unroll 8
    for (int d = 0; d < 64; d++) {
        float v = P[(size_t)(d0 + d) * ALLNUM + j];
        acc += v * v;
    }
    atomicAdd(&g_sumsq[j], acc);
}

// ---------------- input -> bf16 ----------------
__global__ void __launch_bounds__(256) inpcvt_kernel(const float* __restrict__ X) {
    int idx = blockIdx.x * 256 + threadIdx.x;   // over BATCH*DIMK/4
    float4 v = ((const float4*)X)[idx];
    __nv_bfloat162* o = (__nv_bfloat162*)g_inp_bf;
    o[idx * 2 + 0] = __floats2bfloat162_rn(v.x, v.y);
    o[idx * 2 + 1] = __floats2bfloat162_rn(v.z, v.w);
}

// ---------------- centT[j][d] = bf16(P[d][j] / max(||col j||,1e-12)) ----------------
__global__ void __launch_bounds__(256) transpose_kernel(const float* __restrict__ P) {
    __shared__ float tile[32][33];
    int j0 = blockIdx.x * 32, d0 = blockIdx.y * 32;
    int tx = threadIdx.x & 31, ty = threadIdx.x >> 5;   // 32 x 8
    float inv = 1.0f / fmaxf(sqrtf(g_sumsq[j0 + tx]), 1e-12f);
#pragma unroll
    for (int ry = 0; ry < 4; ry++) {
        int r = ty + ry * 8;                            // d within tile
        tile[r][tx] = P[(size_t)(d0 + r) * ALLNUM + j0 + tx] * inv;
    }
    __syncthreads();
#pragma unroll
    for (int ry = 0; ry < 4; ry++) {
        int r = ty + ry * 8;                            // j within tile
        g_centT[(size_t)(j0 + r) * DIMK + d0 + tx] = __float2bfloat16(tile[tx][r]);
    }
}

// ---------------- St[c][d] = bf16( sum_{n<8} centT[8c+n][d] ) ----------------
__global__ void __launch_bounds__(256) classsum_kernel() {
    int idx = blockIdx.x * 256 + threadIdx.x;           // over NCLS * DIMK/2
    int c = idx >> 8, d2 = idx & 255;
    const __nv_bfloat162* src = (const __nv_bfloat162*)g_centT;
    float sx = 0.0f, sy = 0.0f;
#pragma unroll
    for (int n = 0; n < NPROX; n++) {
        float2 v = __bfloat1622float2(src[(size_t)(c * NPROX + n) * (DIMK / 2) + d2]);
        sx += v.x; sy += v.y;
    }
    ((__nv_bfloat162*)g_St)[idx] = __floats2bfloat162_rn(sx, sy);
}

// ---------------- bf16 legacy MMA ----------------
__device__ __forceinline__ void mma16(float* c, const unsigned* a, const unsigned* b) {
    asm volatile(
        "mma.sync.aligned.m16n8k16.row.col.f32.bf16.bf16.f32 "
        "{%0,%1,%2,%3}, {%4,%5,%6,%7}, {%8,%9}, {%0,%1,%2,%3};"
        : "+f"(c[0]), "+f"(c[1]), "+f"(c[2]), "+f"(c[3])
        : "r"(a[0]), "r"(a[1]), "r"(a[2]), "r"(a[3]), "r"(b[0]), "r"(b[1]));
}
#define CPA16(dst, src) \
    asm volatile("cp.async.cg.shared.global [%0], [%1], 16;" ::"r"(dst), "l"(src))

#define SIM_BLOCKS ((BATCH / 128) * (ALLNUM / 128))   // 1024
#define CL_BLOCKS  ((ALLNUM / 128) * (NCLS / 128))    // 512
// per-stage tile: 128 rows x 72 bf16 (64 data + 8 pad) = 18432 B
#define TROWB  144
#define TILE_B (128 * TROWB)
#define STG_B  (2 * TILE_B)
#define GEMM_SMEM (2 * STG_B)                         // 73728 B

// ---------------- fused bf16 GEMM: C = A @ B^T ----------------
// sim path: writes C. CL path: no store — accumulates per-row sum(exp(x-8))
// into g_regpart (atomics) and writes the diagonal CL[j,j>>3] to g_diag.
__global__ void __launch_bounds__(256) gemm_fused() {
    extern __shared__ char dyn[];
    const int tid = threadIdx.x;
    const int lane = tid & 31, wid = tid >> 5;
    const int gid = lane >> 2, tig = lane & 3;
    const int wm = (wid & 3) * 32, wn = (wid >> 2) * 64;

    int b = blockIdx.x;
    const __nv_bfloat16 *A, *B;
    int m0, n0;
    const bool is_sim = (b < SIM_BLOCKS);
    if (is_sim) {
        A = g_inp_bf; B = g_centT;
        m0 = (b / (ALLNUM / 128)) * 128;
        n0 = (b % (ALLNUM / 128)) * 128;
    } else {
        b -= SIM_BLOCKS;
        A = g_centT; B = g_St;
        m0 = (b / (NCLS / 128)) * 128;
        n0 = (b % (NCLS / 128)) * 128;
    }

    unsigned sbase = (unsigned)__cvta_generic_to_shared(dyn);

    float acc[2][8][4] = {};

    auto issue = [&](int st, int k0) {
        unsigned abase = sbase + (unsigned)st * STG_B;
        unsigned bbase = abase + TILE_B;
#pragma unroll
        for (int i = 0; i < 4; i++) {
            int q = tid + i * 256;
            int row = q >> 3, u = q & 7;
            CPA16(abase + (unsigned)(row * TROWB + u * 16),
                  A + (size_t)(m0 + row) * DIMK + k0 + u * 8);
        }
#pragma unroll
        for (int i = 0; i < 4; i++) {
            int q = tid + i * 256;
            int row = q >> 3, u = q & 7;
            CPA16(bbase + (unsigned)(row * TROWB + u * 16),
                  B + (size_t)(n0 + row) * DIMK + k0 + u * 8);
        }
    };

    issue(0, 0);
    asm volatile("cp.async.commit_group;");

    const int NIT = DIMK / 64;                          // 8
    for (int it = 0; it < NIT; it++) {
        if (it + 1 < NIT) issue((it + 1) & 1, (it + 1) * 64);
        asm volatile("cp.async.commit_group;");
        asm volatile("cp.async.wait_group 1;");
        __syncthreads();

        const unsigned* As = (const unsigned*)(dyn + (it & 1) * STG_B);
        const unsigned* Bs = As + TILE_B / 4;
        const int RW = TROWB / 4;                       // 36 words per row
#pragma unroll
        for (int ks = 0; ks < 4; ks++) {
            const int kw = ks * 8;
            unsigned a[2][4], bb[8][2];
#pragma unroll
            for (int mt = 0; mt < 2; mt++) {
                int r = wm + mt * 16 + gid;
                a[mt][0] = As[r * RW + kw + tig];
                a[mt][1] = As[(r + 8) * RW + kw + tig];
                a[mt][2] = As[r * RW + kw + 4 + tig];
                a[mt][3] = As[(r + 8) * RW + kw + 4 + tig];
            }
#pragma unroll
            for (int nt = 0; nt < 8; nt++) {
                int cc = wn + nt * 8 + gid;
                bb[nt][0] = Bs[cc * RW + kw + tig];
                bb[nt][1] = Bs[cc * RW + kw + 4 + tig];
            }
#pragma unroll
            for (int mt = 0; mt < 2; mt++)
#pragma unroll
                for (int nt = 0; nt < 8; nt++)
                    mma16(acc[mt][nt], a[mt], bb[nt]);
        }
        __syncthreads();
    }

    if (is_sim) {
#pragma unroll
        for (int mt = 0; mt < 2; mt++) {
            int r = m0 + wm + mt * 16 + gid;
#pragma unroll
            for (int nt = 0; nt < 8; nt++) {
                int cpos = n0 + wn + nt * 8 + 2 * tig;
                *(float2*)(g_sim + (size_t)r * ALLNUM + cpos) =
                    make_float2(acc[mt][nt][0], acc[mt][nt][1]);
                *(float2*)(g_sim + (size_t)(r + 8) * ALLNUM + cpos) =
                    make_float2(acc[mt][nt][2], acc[mt][nt][3]);
            }
        }
    } else {
        // fused regularizer epilogue: rows are proxies j, cols are classes c
#pragma unroll
        for (int mt = 0; mt < 2; mt++) {
            int r = m0 + wm + mt * 16 + gid;            // proxy row (and r+8)
            float p0 = 0.0f, p1 = 0.0f;                 // exp partials row r, r+8
#pragma unroll
            for (int nt = 0; nt < 8; nt++) {
                int cpos = n0 + wn + nt * 8 + 2 * tig;
                p0 += expf(acc[mt][nt][0] - 8.0f) + expf(acc[mt][nt][1] - 8.0f);
                p1 += expf(acc[mt][nt][2] - 8.0f) + expf(acc[mt][nt][3] - 8.0f);
                if (cpos     == (r >> 3))       g_diag[r]     = acc[mt][nt][0];
                if (cpos + 1 == (r >> 3))       g_diag[r]     = acc[mt][nt][1];
                if (cpos     == ((r + 8) >> 3)) g_diag[r + 8] = acc[mt][nt][2];
                if (cpos + 1 == ((r + 8) >> 3)) g_diag[r + 8] = acc[mt][nt][3];
            }
            // reduce across tig group (lanes gid*4 + {0..3})
            p0 += __shfl_xor_sync(0xFFFFFFFFu, p0, 1);
            p0 += __shfl_xor_sync(0xFFFFFFFFu, p0, 2);
            p1 += __shfl_xor_sync(0xFFFFFFFFu, p1, 1);
            p1 += __shfl_xor_sync(0xFFFFFFFFu, p1, 2);
            if (tig == 0) {
                atomicAdd(&g_regpart[r], p0);
                atomicAdd(&g_regpart[r + 8], p1);
            }
        }
    }
}

// ---------------- per-row: exact top-410 radix select + class-sum softmax CE ----------------
__device__ __forceinline__ unsigned int fkey(float v) {
    unsigned int b = __float_as_uint(v);
    return b ^ ((unsigned int)((int)b >> 31) | 0x80000000u);
}

__global__ void __launch_bounds__(256) topk_classify_kernel(const void* targ) {
    __shared__ float s_sim[ALLNUM];
    __shared__ unsigned int s_hist[256];
    __shared__ float s_red[256];
    __shared__ float s_et;
    const int row = blockIdx.x;
    const int tid = threadIdx.x;

    int t;
    if (g_tgt64) t = (int)((const long long*)targ)[row];
    else         t = ((const int*)targ)[row];

    // fused: load sim row into smem AND build radix pass-1 histogram (bits 31:24)
    s_hist[tid] = 0u;
    __syncthreads();
    {
        const float4* src = (const float4*)(g_sim + (size_t)row * ALLNUM);
        float4* dst = (float4*)s_sim;
        for (int i = tid; i < ALLNUM / 4; i += 256) {
            float4 v = src[i];
            dst[i] = v;
            int j = i * 4;
            float a0 = v.x + (((j     >> 3) == t) ? 1000.0f : 0.0f);
            float a1 = v.y + ((((j+1) >> 3) == t) ? 1000.0f : 0.0f);
            float a2 = v.z + ((((j+2) >> 3) == t) ? 1000.0f : 0.0f);
            float a3 = v.w + ((((j+3) >> 3) == t) ? 1000.0f : 0.0f);
            atomicAdd(&s_hist[fkey(a0) >> 24], 1u);
            atomicAdd(&s_hist[fkey(a1) >> 24], 1u);
            atomicAdd(&s_hist[fkey(a2) >> 24], 1u);
            atomicAdd(&s_hist[fkey(a3) >> 24], 1u);
        }
    }
    __syncthreads();

    unsigned int prefix = 0u;
    int krem = TOPK;
    {   // select from pass-1 histogram (all threads redundantly)
        int cum = 0, chosen = 0;
        for (int b = 255; b >= 0; b--) {
            int h = (int)s_hist[b];
            if (cum + h >= krem) { chosen = b; break; }
            cum += h;
        }
        krem -= cum;
        prefix = (unsigned)chosen << 24;
    }

#pragma unroll
    for (int shift = 16; shift >= 0; shift -= 8) {
        __syncthreads();
        s_hist[tid] = 0u;
        __syncthreads();
        unsigned int mask_hi = 0xFFFFFFFFu << (shift + 8);
        for (int j = tid; j < ALLNUM; j += 256) {
            float v = s_sim[j] + (((j >> 3) == t) ? 1000.0f : 0.0f);
            unsigned int key = fkey(v);
            if ((key & mask_hi) == prefix)
                atomicAdd(&s_hist[(key >> shift) & 0xFFu], 1u);
        }
        __syncthreads();
        int cum = 0, chosen = 0;
        for (int b = 255; b >= 0; b--) {
            int h = (int)s_hist[b];
            if (cum + h >= krem) { chosen = b; break; }
            cum += h;
        }
        krem -= cum;
        prefix |= (unsigned int)chosen << shift;
    }
    const unsigned int T = prefix;

    float esum = 0.0f;
    for (int c = tid; c < NCLS; c += 256) {
        float aug = (c == t) ? 1000.0f : 0.0f;
        float sum = 0.0f;
#pragma unroll
        for (int n = 0; n < NPROX; n++) {
            float v = s_sim[c * NPROX + n];
            if (fkey(v + aug) >= T) sum += v;
        }
        float e = (sum != 0.0f) ? expf(sum) : 0.0f;
        if (c == t) s_et = e;
        esum += e;
    }
    s_red[tid] = esum;
    __syncthreads();
    for (int s = 128; s > 0; s >>= 1) {
        if (tid < s) s_red[tid] += s_red[tid + s];
        __syncthreads();
    }
    if (tid == 0) {
        float p = s_et / (1e-8f + s_red[0]);
        g_rowloss[row] = -logf(p + 1e-20f);
    }
}

// ---------------- final reduction (classify mean + reg from fused partials) ----------------
__global__ void __launch_bounds__(256) final_kernel(float* out, int out_size) {
    __shared__ float s1[256], s2[256];
    const int tid = threadIdx.x;
    float a = 0.0f, r = 0.0f;
    for (int i = tid; i < BATCH; i += 256)  a += g_rowloss[i];
    for (int i = tid; i < ALLNUM; i += 256)
        r += 8.0f + logf(g_regpart[i]) - g_diag[i];
    s1[tid] = a; s2[tid] = r;
    __syncthreads();
    for (int s = 128; s > 0; s >>= 1) {
        if (tid < s) { s1[tid] += s1[tid + s]; s2[tid] += s2[tid + s]; }
        __syncthreads();
    }
    if (tid == 0) {
        float lc  = s1[0] / (float)BATCH;
        float reg = s2[0] / (float)ALLNUM;
        out[0] = lc + LAM * reg;
        if (out_size > 1) out[1] = lc;
    }
}

// ---------------- launch ----------------
extern "C" void kernel_launch(void* const* d_in, const int* in_sizes, int n_in,
                              void* d_out, int out_size) {
    const float* input   = (const float*)d_in[0];      // [2048, 512]
    const void*  target  = d_in[1];                    // [2048] int32 or int64
    const float* proxies = (const float*)d_in[2];      // [512, 8192]
    float* out = (float*)d_out;

    float *sumsq, *regpart;
    cudaGetSymbolAddress((void**)&sumsq,   g_sumsq);
    cudaGetSymbolAddress((void**)&regpart, g_regpart);

    cudaFuncSetAttribute(gemm_fused,
                         cudaFuncAttributeMaxDynamicSharedMemorySize, GEMM_SMEM);

    detect_kernel<<<1, 256>>>((const unsigned int*)target);
    cudaMemsetAsync(sumsq, 0, ALLNUM * sizeof(float));
    cudaMemsetAsync(regpart, 0, ALLNUM * sizeof(float));
    {
        dim3 grid(ALLNUM / 256, DIMK / 64);
        sumsq_kernel<<<grid, 256>>>(proxies);
    }
    inpcvt_kernel<<<BATCH * DIMK / 4 / 256, 256>>>(input);
    {
        dim3 grid(ALLNUM / 32, DIMK / 32);
        transpose_kernel<<<grid, 256>>>(proxies);
    }
    classsum_kernel<<<NCLS * (DIMK / 2) / 256, 256>>>();

    gemm_fused<<<SIM_BLOCKS + CL_BLOCKS, 256, GEMM_SMEM>>>();

    topk_classify_kernel<<<BATCH, 256>>>(target);
    final_kernel<<<1, 256>>>(out, out_size);
}

// round 17
// speedup vs baseline: 5.3008x; 1.2324x over previous
#include <cuda_runtime.h>
#include <cuda_bf16.h>
#include <math.h>

#define DIMK   512
#define ALLNUM 8192
#define BATCH  2048
#define NCLS   1024
#define NPROX  8
#define TOPK   410
#define LAM    0.3f

// ---------------- scratch (device globals: no allocation allowed) ----------------
__device__ __nv_bfloat16 g_inp_bf[BATCH * DIMK];    //  2 MB  input, bf16
__device__ __nv_bfloat16 g_centT[ALLNUM * DIMK];    //  8 MB  normalized centers^T [8192,512]
__device__ __nv_bfloat16 g_St[NCLS * DIMK];         //  1 MB  class-summed centers^T [1024,512]
__device__ float g_sim[BATCH * ALLNUM];             // 64 MB
__device__ float g_rowloss[BATCH];
__device__ float g_regpart[ALLNUM];                 // per-proxy sum of exp(CL-8)
__device__ float g_diag[ALLNUM];                    // CL[j, j>>3]
__device__ int   g_tgt64;

// ---------------- target dtype detection (int64 vs int32) ----------------
__global__ void detect_kernel(const unsigned int* tw) {
    __shared__ unsigned int any;
    if (threadIdx.x == 0) any = 0u;
    __syncthreads();
    unsigned int local = 0u;
    for (int i = threadIdx.x; i < 1024; i += blockDim.x) local |= tw[2 * i + 1];
    atomicOr(&any, local);
    __syncthreads();
    if (threadIdx.x == 0) g_tgt64 = (any == 0u) ? 1 : 0;
}

// ---------------- input -> bf16 ----------------
__global__ void __launch_bounds__(256) inpcvt_kernel(const float* __restrict__ X) {
    int idx = blockIdx.x * 256 + threadIdx.x;   // over BATCH*DIMK/4
    float4 v = ((const float4*)X)[idx];
    __nv_bfloat162* o = (__nv_bfloat162*)g_inp_bf;
    o[idx * 2 + 0] = __floats2bfloat162_rn(v.x, v.y);
    o[idx * 2 + 1] = __floats2bfloat162_rn(v.z, v.w);
}

// ---------------- fused: column norm + normalize + transpose -> bf16 ----------------
// Block owns 32 proxy columns j0..j0+31 (all 512 d). One pass over P.
// smem row stride 521 (coprime with 32 -> conflict-free both phases).
#define NT_STRIDE 521
#define NT_SMEM   ((32 * NT_STRIDE + 256 + 32) * 4)
__global__ void __launch_bounds__(256) normtrans_kernel(const float* __restrict__ P) {
    extern __shared__ float sm[];                    // [32][521]
    float* s_part = sm + 32 * NT_STRIDE;             // [8][32]
    float* s_inv  = s_part + 256;                    // [32]
    const int tid = threadIdx.x;
    const int j0 = blockIdx.x * 32;
    const int tx = tid & 31, ty = tid >> 5;

    // load phase: warp ty reads d = ty, ty+8, ... ; lanes cover 32 consecutive j
#pragma unroll 8
    for (int d = ty; d < DIMK; d += 8)
        sm[tx * NT_STRIDE + d] = P[(size_t)d * ALLNUM + j0 + tx];
    __syncthreads();

    // sum-of-squares: thread (j = tid&31, slice = tid>>5) covers 64 d
    {
        int j = tid & 31, sl = tid >> 5;
        const float* row = sm + j * NT_STRIDE + sl * 64;
        float a = 0.0f;
#pragma unroll 16
        for (int i = 0; i < 64; i++) a += row[i] * row[i];
        s_part[sl * 32 + j] = a;
    }
    __syncthreads();
    if (tid < 32) {
        float s = 0.0f;
#pragma unroll
        for (int sl = 0; sl < 8; sl++) s += s_part[sl * 32 + tid];
        s_inv[tid] = 1.0f / fmaxf(sqrtf(s), 1e-12f);
    }
    __syncthreads();

    // write phase: thread (j = tid>>3, l8 = tid&7); per-iter 8 consecutive
    // threads cover 128B contiguous of one centT row -> coalesced
    {
        int j = tid >> 3, l8 = tid & 7;
        float inv = s_inv[j];
        __nv_bfloat16* dst = g_centT + (size_t)(j0 + j) * DIMK;
        const float* src = sm + j * NT_STRIDE;
#pragma unroll
        for (int i = 0; i < 8; i++) {
            int d = i * 64 + l8 * 8;
            __nv_bfloat162 o[4];
#pragma unroll
            for (int q = 0; q < 4; q++)
                o[q] = __floats2bfloat162_rn(src[d + 2 * q] * inv,
                                             src[d + 2 * q + 1] * inv);
            *(uint4*)(dst + d) = *(const uint4*)o;
        }
    }
}

// ---------------- St[c][d] = bf16( sum_{n<8} centT[8c+n][d] ) ----------------
__global__ void __launch_bounds__(256) classsum_kernel() {
    int idx = blockIdx.x * 256 + threadIdx.x;           // over NCLS * DIMK/2
    int c = idx >> 8, d2 = idx & 255;
    const __nv_bfloat162* src = (const __nv_bfloat162*)g_centT;
    float sx = 0.0f, sy = 0.0f;
#pragma unroll
    for (int n = 0; n < NPROX; n++) {
        float2 v = __bfloat1622float2(src[(size_t)(c * NPROX + n) * (DIMK / 2) + d2]);
        sx += v.x; sy += v.y;
    }
    ((__nv_bfloat162*)g_St)[idx] = __floats2bfloat162_rn(sx, sy);
}

// ---------------- bf16 legacy MMA ----------------
__device__ __forceinline__ void mma16(float* c, const unsigned* a, const unsigned* b) {
    asm volatile(
        "mma.sync.aligned.m16n8k16.row.col.f32.bf16.bf16.f32 "
        "{%0,%1,%2,%3}, {%4,%5,%6,%7}, {%8,%9}, {%0,%1,%2,%3};"
        : "+f"(c[0]), "+f"(c[1]), "+f"(c[2]), "+f"(c[3])
        : "r"(a[0]), "r"(a[1]), "r"(a[2]), "r"(a[3]), "r"(b[0]), "r"(b[1]));
}
#define CPA16(dst, src) \
    asm volatile("cp.async.cg.shared.global [%0], [%1], 16;" ::"r"(dst), "l"(src))

#define SIM_BLOCKS ((BATCH / 128) * (ALLNUM / 128))   // 1024
#define CL_BLOCKS  ((ALLNUM / 128) * (NCLS / 128))    // 512
#define TROWB  144
#define TILE_B (128 * TROWB)
#define STG_B  (2 * TILE_B)
#define GEMM_SMEM (2 * STG_B)                         // 73728 B

// ---------------- fused bf16 GEMM: C = A @ B^T ----------------
__global__ void __launch_bounds__(256) gemm_fused() {
    extern __shared__ char dyn[];
    const int tid = threadIdx.x;
    const int lane = tid & 31, wid = tid >> 5;
    const int gid = lane >> 2, tig = lane & 3;
    const int wm = (wid & 3) * 32, wn = (wid >> 2) * 64;

    int b = blockIdx.x;
    const __nv_bfloat16 *A, *B;
    int m0, n0;
    const bool is_sim = (b < SIM_BLOCKS);
    if (is_sim) {
        A = g_inp_bf; B = g_centT;
        m0 = (b / (ALLNUM / 128)) * 128;
        n0 = (b % (ALLNUM / 128)) * 128;
    } else {
        b -= SIM_BLOCKS;
        A = g_centT; B = g_St;
        m0 = (b / (NCLS / 128)) * 128;
        n0 = (b % (NCLS / 128)) * 128;
    }

    unsigned sbase = (unsigned)__cvta_generic_to_shared(dyn);
    float acc[2][8][4] = {};

    auto issue = [&](int st, int k0) {
        unsigned abase = sbase + (unsigned)st * STG_B;
        unsigned bbase = abase + TILE_B;
#pragma unroll
        for (int i = 0; i < 4; i++) {
            int q = tid + i * 256;
            int row = q >> 3, u = q & 7;
            CPA16(abase + (unsigned)(row * TROWB + u * 16),
                  A + (size_t)(m0 + row) * DIMK + k0 + u * 8);
        }
#pragma unroll
        for (int i = 0; i < 4; i++) {
            int q = tid + i * 256;
            int row = q >> 3, u = q & 7;
            CPA16(bbase + (unsigned)(row * TROWB + u * 16),
                  B + (size_t)(n0 + row) * DIMK + k0 + u * 8);
        }
    };

    issue(0, 0);
    asm volatile("cp.async.commit_group;");

    const int NIT = DIMK / 64;                          // 8
    for (int it = 0; it < NIT; it++) {
        if (it + 1 < NIT) issue((it + 1) & 1, (it + 1) * 64);
        asm volatile("cp.async.commit_group;");
        asm volatile("cp.async.wait_group 1;");
        __syncthreads();

        const unsigned* As = (const unsigned*)(dyn + (it & 1) * STG_B);
        const unsigned* Bs = As + TILE_B / 4;
        const int RW = TROWB / 4;                       // 36 words per row
#pragma unroll
        for (int ks = 0; ks < 4; ks++) {
            const int kw = ks * 8;
            unsigned a[2][4], bb[8][2];
#pragma unroll
            for (int mt = 0; mt < 2; mt++) {
                int r = wm + mt * 16 + gid;
                a[mt][0] = As[r * RW + kw + tig];
                a[mt][1] = As[(r + 8) * RW + kw + tig];
                a[mt][2] = As[r * RW + kw + 4 + tig];
                a[mt][3] = As[(r + 8) * RW + kw + 4 + tig];
            }
#pragma unroll
            for (int nt = 0; nt < 8; nt++) {
                int cc = wn + nt * 8 + gid;
                bb[nt][0] = Bs[cc * RW + kw + tig];
                bb[nt][1] = Bs[cc * RW + kw + 4 + tig];
            }
#pragma unroll
            for (int mt = 0; mt < 2; mt++)
#pragma unroll
                for (int nt = 0; nt < 8; nt++)
                    mma16(acc[mt][nt], a[mt], bb[nt]);
        }
        __syncthreads();
    }

    if (is_sim) {
#pragma unroll
        for (int mt = 0; mt < 2; mt++) {
            int r = m0 + wm + mt * 16 + gid;
#pragma unroll
            for (int nt = 0; nt < 8; nt++) {
                int cpos = n0 + wn + nt * 8 + 2 * tig;
                *(float2*)(g_sim + (size_t)r * ALLNUM + cpos) =
                    make_float2(acc[mt][nt][0], acc[mt][nt][1]);
                *(float2*)(g_sim + (size_t)(r + 8) * ALLNUM + cpos) =
                    make_float2(acc[mt][nt][2], acc[mt][nt][3]);
            }
        }
    } else {
        // fused regularizer epilogue: rows = proxies j, cols = classes c
#pragma unroll
        for (int mt = 0; mt < 2; mt++) {
            int r = m0 + wm + mt * 16 + gid;
            float p0 = 0.0f, p1 = 0.0f;
#pragma unroll
            for (int nt = 0; nt < 8; nt++) {
                int cpos = n0 + wn + nt * 8 + 2 * tig;
                p0 += expf(acc[mt][nt][0] - 8.0f) + expf(acc[mt][nt][1] - 8.0f);
                p1 += expf(acc[mt][nt][2] - 8.0f) + expf(acc[mt][nt][3] - 8.0f);
                if (cpos     == (r >> 3))       g_diag[r]     = acc[mt][nt][0];
                if (cpos + 1 == (r >> 3))       g_diag[r]     = acc[mt][nt][1];
                if (cpos     == ((r + 8) >> 3)) g_diag[r + 8] = acc[mt][nt][2];
                if (cpos + 1 == ((r + 8) >> 3)) g_diag[r + 8] = acc[mt][nt][3];
            }
            p0 += __shfl_xor_sync(0xFFFFFFFFu, p0, 1);
            p0 += __shfl_xor_sync(0xFFFFFFFFu, p0, 2);
            p1 += __shfl_xor_sync(0xFFFFFFFFu, p1, 1);
            p1 += __shfl_xor_sync(0xFFFFFFFFu, p1, 2);
            if (tig == 0) {
                atomicAdd(&g_regpart[r], p0);
                atomicAdd(&g_regpart[r + 8], p1);
            }
        }
    }
}

// ---------------- per-row: exact top-410 radix select + class-sum softmax CE ----------------
__device__ __forceinline__ unsigned int fkey(float v) {
    unsigned int b = __float_as_uint(v);
    return b ^ ((unsigned int)((int)b >> 31) | 0x80000000u);
}

__global__ void __launch_bounds__(256) topk_classify_kernel(const void* targ) {
    __shared__ float s_sim[ALLNUM];
    __shared__ unsigned int s_hist[256];
    __shared__ float s_red[256];
    __shared__ float s_et;
    __shared__ int s_sel, s_krem;
    const int row = blockIdx.x;
    const int tid = threadIdx.x;

    int t;
    if (g_tgt64) t = (int)((const long long*)targ)[row];
    else         t = ((const int*)targ)[row];

    // parallel bucket selection (warp 0): chunk sums + shfl suffix scan +
    // walk within the unique chosen chunk. Replaces 255-iter serial scan.
    auto select = [&](int krem_in) {
        if (tid < 32) {
            unsigned chunk = 0;
#pragma unroll
            for (int i = 0; i < 8; i++) chunk += s_hist[tid * 8 + i];
            unsigned ss = chunk;
#pragma unroll
            for (int off = 1; off < 32; off <<= 1) {
                unsigned v = __shfl_down_sync(0xFFFFFFFFu, ss, off);
                if (tid + off < 32) ss += v;
            }
            unsigned above = ss - chunk;
            if (ss >= (unsigned)krem_in && above < (unsigned)krem_in) {
                unsigned cum = above;
#pragma unroll
                for (int i = 7; i >= 0; i--) {
                    unsigned h = s_hist[tid * 8 + i];
                    if (cum + h >= (unsigned)krem_in) {
                        s_sel = tid * 8 + i;
                        s_krem = krem_in - (int)cum;
                        break;
                    }
                    cum += h;
                }
            }
        }
        __syncthreads();
    };

    // fused: load sim row into smem AND build radix pass-1 histogram (bits 31:24)
    s_hist[tid] = 0u;
    __syncthreads();
    {
        const float4* src = (const float4*)(g_sim + (size_t)row * ALLNUM);
        float4* dst = (float4*)s_sim;
        for (int i = tid; i < ALLNUM / 4; i += 256) {
            float4 v = src[i];
            dst[i] = v;
            int j = i * 4;
            float a0 = v.x + (((j     >> 3) == t) ? 1000.0f : 0.0f);
            float a1 = v.y + ((((j+1) >> 3) == t) ? 1000.0f : 0.0f);
            float a2 = v.z + ((((j+2) >> 3) == t) ? 1000.0f : 0.0f);
            float a3 = v.w + ((((j+3) >> 3) == t) ? 1000.0f : 0.0f);
            atomicAdd(&s_hist[fkey(a0) >> 24], 1u);
            atomicAdd(&s_hist[fkey(a1) >> 24], 1u);
            atomicAdd(&s_hist[fkey(a2) >> 24], 1u);
            atomicAdd(&s_hist[fkey(a3) >> 24], 1u);
        }
    }
    __syncthreads();

    select(TOPK);
    unsigned prefix = (unsigned)s_sel << 24;
    int krem = s_krem;

#pragma unroll
    for (int shift = 16; shift >= 0; shift -= 8) {
        __syncthreads();
        s_hist[tid] = 0u;
        __syncthreads();
        unsigned int mask_hi = 0xFFFFFFFFu << (shift + 8);
        for (int j = tid; j < ALLNUM; j += 256) {
            float v = s_sim[j] + (((j >> 3) == t) ? 1000.0f : 0.0f);
            unsigned int key = fkey(v);
            if ((key & mask_hi) == prefix)
                atomicAdd(&s_hist[(key >> shift) & 0xFFu], 1u);
        }
        __syncthreads();
        select(krem);
        prefix |= (unsigned)s_sel << shift;
        krem = s_krem;
    }
    const unsigned int T = prefix;

    float esum = 0.0f;
    for (int c = tid; c < NCLS; c += 256) {
        float aug = (c == t) ? 1000.0f : 0.0f;
        float sum = 0.0f;
#pragma unroll
        for (int n = 0; n < NPROX; n++) {
            float v = s_sim[c * NPROX + n];
            if (fkey(v + aug) >= T) sum += v;
        }
        float e = (sum != 0.0f) ? expf(sum) : 0.0f;
        if (c == t) s_et = e;
        esum += e;
    }
    s_red[tid] = esum;
    __syncthreads();
    for (int s = 128; s > 0; s >>= 1) {
        if (tid < s) s_red[tid] += s_red[tid + s];
        __syncthreads();
    }
    if (tid == 0) {
        float p = s_et / (1e-8f + s_red[0]);
        g_rowloss[row] = -logf(p + 1e-20f);
    }
}

// ---------------- final reduction ----------------
__global__ void __launch_bounds__(256) final_kernel(float* out, int out_size) {
    __shared__ float s1[256], s2[256];
    const int tid = threadIdx.x;
    float a = 0.0f, r = 0.0f;
    for (int i = tid; i < BATCH; i += 256)  a += g_rowloss[i];
    for (int i = tid; i < ALLNUM; i += 256)
        r += 8.0f + logf(g_regpart[i]) - g_diag[i];
    s1[tid] = a; s2[tid] = r;
    __syncthreads();
    for (int s = 128; s > 0; s >>= 1) {
        if (tid < s) { s1[tid] += s1[tid + s]; s2[tid] += s2[tid + s]; }
        __syncthreads();
    }
    if (tid == 0) {
        float lc  = s1[0] / (float)BATCH;
        float reg = s2[0] / (float)ALLNUM;
        out[0] = lc + LAM * reg;
        if (out_size > 1) out[1] = lc;
    }
}

// ---------------- launch ----------------
extern "C" void kernel_launch(void* const* d_in, const int* in_sizes, int n_in,
                              void* d_out, int out_size) {
    const float* input   = (const float*)d_in[0];      // [2048, 512]
    const void*  target  = d_in[1];                    // [2048] int32 or int64
    const float* proxies = (const float*)d_in[2];      // [512, 8192]
    float* out = (float*)d_out;

    float* regpart;
    cudaGetSymbolAddress((void**)&regpart, g_regpart);

    cudaFuncSetAttribute(gemm_fused,
                         cudaFuncAttributeMaxDynamicSharedMemorySize, GEMM_SMEM);
    cudaFuncSetAttribute(normtrans_kernel,
                         cudaFuncAttributeMaxDynamicSharedMemorySize, NT_SMEM);

    detect_kernel<<<1, 256>>>((const unsigned int*)target);
    cudaMemsetAsync(regpart, 0, ALLNUM * sizeof(float));
    inpcvt_kernel<<<BATCH * DIMK / 4 / 256, 256>>>(input);
    normtrans_kernel<<<ALLNUM / 32, 256, NT_SMEM>>>(proxies);
    classsum_kernel<<<NCLS * (DIMK / 2) / 256, 256>>>();

    gemm_fused<<<SIM_BLOCKS + CL_BLOCKS, 256, GEMM_SMEM>>>();

    topk_classify_kernel<<<BATCH, 256>>>(target);
    final_kernel<<<1, 256>>>(out, out_size);
}